// round 7
// baseline (speedup 1.0000x reference)
#include <cuda_runtime.h>
#include <cuda_bf16.h>
#include <math.h>
#include <stdint.h>

#define NROWS 4096
#define DIM   1024
#define TEMPF 0.05f
#define EPSF  1e-8f

// split-precision: logical K = 3072 (hi*hi + lo*hi + hi*lo), stored K = 2048 [hi|lo]
#define KSTORE 2048
#define BM 128
#define BN 128
#define BK 64                       // bf16 per chunk = 128 bytes/row (SW128 atom)
#define NCHUNKS 48                  // logical chunks (K=3072)
#define NSTAGES 3
#define A_STAGE_BYTES (BM * 128)    // 16 KB
#define B_STAGE_BYTES (BN * 128)    // 16 KB
#define STAGE_BYTES   (A_STAGE_BYTES + B_STAGE_BYTES)   // 32 KB
#define SMEM_DYN_BYTES (NSTAGES * STAGE_BYTES)          // 96 KB -> 2 CTAs/SM

// -------- device scratch (no runtime allocation allowed) --------
__device__ __nv_bfloat16 g_a[(size_t)NROWS * KSTORE];   // cn:  [hi | lo]
__device__ __nv_bfloat16 g_b[(size_t)NROWS * KSTORE];   // chn: [hi | lo]
__device__ __align__(16) float g_row_val[NROWS];

// ============================================================
// helpers
// ============================================================
__device__ __forceinline__ uint32_t smem_u32(const void* p) {
    uint32_t a;
    asm("{ .reg .u64 t; cvta.to.shared.u64 t, %1; cvt.u32.u64 %0, t; }"
        : "=r"(a) : "l"(p));
    return a;
}

#define SW128(x) ((x) ^ (((x) >> 3) & 0x70))

__device__ __forceinline__ void cp_async16(uint32_t dst, const void* src) {
    asm volatile("cp.async.cg.shared.global [%0], [%1], 16;\n" :: "r"(dst), "l"(src));
}

__device__ __forceinline__ void ldsm_x4(uint32_t addr, uint32_t& r0, uint32_t& r1,
                                        uint32_t& r2, uint32_t& r3) {
    asm volatile("ldmatrix.sync.aligned.m8n8.x4.shared.b16 {%0,%1,%2,%3}, [%4];"
                 : "=r"(r0), "=r"(r1), "=r"(r2), "=r"(r3) : "r"(addr));
}

__device__ __forceinline__ void mma16816(float& c0, float& c1, float& c2, float& c3,
                                         uint32_t a0, uint32_t a1, uint32_t a2, uint32_t a3,
                                         uint32_t b0, uint32_t b1) {
    asm volatile(
        "mma.sync.aligned.m16n8k16.row.col.f32.bf16.bf16.f32 "
        "{%0,%1,%2,%3}, {%4,%5,%6,%7}, {%8,%9}, {%0,%1,%2,%3};"
        : "+f"(c0), "+f"(c1), "+f"(c2), "+f"(c3)
        : "r"(a0), "r"(a1), "r"(a2), "r"(a3), "r"(b0), "r"(b1));
}

// ============================================================
// Kernel 1: row-normalize + bf16 hi/lo split into g_a / g_b
// ============================================================
__global__ __launch_bounds__(256)
void normalize_split_kernel(const float* __restrict__ c, const float* __restrict__ ch) {
    int row = blockIdx.x;
    bool isC = (row < NROWS);
    int r = isC ? row : row - NROWS;
    const float4* srow = (const float4*)((isC ? c : ch) + (size_t)r * DIM);

    int t = threadIdx.x;
    float4 v = srow[t];
    float ssq = v.x * v.x + v.y * v.y + v.z * v.z + v.w * v.w;

    #pragma unroll
    for (int o = 16; o > 0; o >>= 1)
        ssq += __shfl_xor_sync(0xffffffffu, ssq, o);

    __shared__ float wsum[8];
    if ((t & 31) == 0) wsum[t >> 5] = ssq;
    __syncthreads();
    float tot = 0.f;
    #pragma unroll
    for (int w = 0; w < 8; w++) tot += wsum[w];

    float rinv = 1.0f / fmaxf(sqrtf(tot), EPSF);
    float x[4] = { v.x * rinv, v.y * rinv, v.z * rinv, v.w * rinv };

    union { __nv_bfloat16 h[4]; uint2 u; } phi, plo;
    #pragma unroll
    for (int i = 0; i < 4; i++) {
        phi.h[i] = __float2bfloat16(x[i]);
        plo.h[i] = __float2bfloat16(x[i] - __bfloat162float(phi.h[i]));
    }

    __nv_bfloat16* dst = (isC ? g_a : g_b) + (size_t)r * KSTORE + t * 4;
    *(uint2*)(dst)       = phi.u;   // hi block  [0, DIM)
    *(uint2*)(dst + DIM) = plo.u;   // lo block  [DIM, 2*DIM)
}

// ============================================================
// Kernel 2: mma.sync bf16 GEMM, 128x128 tile, logical K=3072
// 8 warps as 4(M) x 2(N); warp tile 32x64; mma m16n8k16
// single sync per chunk + fragment double-buffering across k16 steps
// ============================================================
__device__ __forceinline__ void load_chunk(const __nv_bfloat16* gA, const __nv_bfloat16* gB,
                                           int kc, uint32_t sA, uint32_t sB, int t) {
    // logical chunk -> stored chunk (hi chunks = [0,16), lo chunks = [16,32))
    int a_ke = (kc - (kc >= 32 ? 32 : 0)) * BK;   // A: hi, lo, hi
    int b_ke = (kc - (kc >= 16 ? 16 : 0)) * BK;   // B: hi, hi, lo
    #pragma unroll
    for (int i = 0; i < 4; i++) {
        int idx = i * 256 + t;
        int r = idx >> 3, cb = idx & 7;
        cp_async16(sA + SW128(r * 128 + cb * 16), gA + (size_t)r * KSTORE + a_ke + cb * 8);
    }
    #pragma unroll
    for (int i = 0; i < 4; i++) {
        int idx = i * 256 + t;
        int r = idx >> 3, cb = idx & 7;
        cp_async16(sB + SW128(r * 128 + cb * 16), gB + (size_t)r * KSTORE + b_ke + cb * 8);
    }
    asm volatile("cp.async.commit_group;\n" ::: "memory");
}

__global__ __launch_bounds__(256, 2)
void gemm_kernel(float* __restrict__ out) {
    extern __shared__ char dyn_smem[];

    const int t    = threadIdx.x;
    const int wid  = t >> 5;
    const int lane = t & 31;
    const int wm   = wid >> 1;          // 0..3  (M warp)
    const int wn   = wid & 1;           // 0..1  (N warp)
    const int bx   = blockIdx.x;        // N tile
    const int by   = blockIdx.y;        // M tile

    uint32_t smem = smem_u32(dyn_smem);

    const __nv_bfloat16* gA = g_a + (size_t)by * BM * KSTORE;
    const __nv_bfloat16* gB = g_b + (size_t)bx * BN * KSTORE;

    float acc[2][8][4];
    #pragma unroll
    for (int mi = 0; mi < 2; mi++)
        #pragma unroll
        for (int ni = 0; ni < 8; ni++)
            #pragma unroll
            for (int q = 0; q < 4; q++) acc[mi][ni][q] = 0.f;

    // prologue: 2 chunks in flight
    load_chunk(gA, gB, 0, smem, smem + A_STAGE_BYTES, t);
    load_chunk(gA, gB, 1, smem + STAGE_BYTES, smem + STAGE_BYTES + A_STAGE_BYTES, t);

    const int a_row_in16 = lane & 15;
    const int a_kadd     = ((lane >> 4) & 1) * 16;
    const int b_row_in16 = (lane & 7) + (((lane >> 4) & 1) << 3);
    const int b_kadd     = ((lane >> 3) & 1) * 16;

    uint32_t af[2][2][4];   // [buf][mi][frag]
    uint32_t bf[2][4][4];   // [buf][nj][frag]

    for (int kc = 0; kc < NCHUNKS; kc++) {
        // wait for chunk kc (leave kc+1 in flight), then one sync
        asm volatile("cp.async.wait_group 1;\n" ::: "memory");
        __syncthreads();
        // prefetch kc+2 into the stage last read at iteration kc-1 (safe: all
        // threads passed the sync above after finishing those reads)
        if (kc + 2 < NCHUNKS) {
            int s = (kc + 2) % NSTAGES;
            load_chunk(gA, gB, kc + 2, smem + s * STAGE_BYTES,
                       smem + s * STAGE_BYTES + A_STAGE_BYTES, t);
        } else {
            asm volatile("cp.async.commit_group;\n" ::: "memory");
        }

        uint32_t sA = smem + (kc % NSTAGES) * STAGE_BYTES;
        uint32_t sB = sA + A_STAGE_BYTES;

        // load fragments for ks=0
        #pragma unroll
        for (int mi = 0; mi < 2; mi++) {
            int row = wm * 32 + mi * 16 + a_row_in16;
            ldsm_x4(sA + SW128(row * 128 + a_kadd),
                    af[0][mi][0], af[0][mi][1], af[0][mi][2], af[0][mi][3]);
        }
        #pragma unroll
        for (int nj = 0; nj < 4; nj++) {
            int row = wn * 64 + nj * 16 + b_row_in16;
            ldsm_x4(sB + SW128(row * 128 + b_kadd),
                    bf[0][nj][0], bf[0][nj][1], bf[0][nj][2], bf[0][nj][3]);
        }

        #pragma unroll
        for (int ks = 0; ks < 4; ks++) {
            const int cur = ks & 1, nxt = cur ^ 1;
            // prefetch fragments for ks+1 before issuing MMAs of ks
            if (ks < 3) {
                const int kb = (ks + 1) * 32;
                #pragma unroll
                for (int mi = 0; mi < 2; mi++) {
                    int row = wm * 32 + mi * 16 + a_row_in16;
                    ldsm_x4(sA + SW128(row * 128 + kb + a_kadd),
                            af[nxt][mi][0], af[nxt][mi][1], af[nxt][mi][2], af[nxt][mi][3]);
                }
                #pragma unroll
                for (int nj = 0; nj < 4; nj++) {
                    int row = wn * 64 + nj * 16 + b_row_in16;
                    ldsm_x4(sB + SW128(row * 128 + kb + b_kadd),
                            bf[nxt][nj][0], bf[nxt][nj][1], bf[nxt][nj][2], bf[nxt][nj][3]);
                }
            }
            #pragma unroll
            for (int mi = 0; mi < 2; mi++)
                #pragma unroll
                for (int nj = 0; nj < 4; nj++) {
                    mma16816(acc[mi][nj * 2 + 0][0], acc[mi][nj * 2 + 0][1],
                             acc[mi][nj * 2 + 0][2], acc[mi][nj * 2 + 0][3],
                             af[cur][mi][0], af[cur][mi][1], af[cur][mi][2], af[cur][mi][3],
                             bf[cur][nj][0], bf[cur][nj][1]);
                    mma16816(acc[mi][nj * 2 + 1][0], acc[mi][nj * 2 + 1][1],
                             acc[mi][nj * 2 + 1][2], acc[mi][nj * 2 + 1][3],
                             af[cur][mi][0], af[cur][mi][1], af[cur][mi][2], af[cur][mi][3],
                             bf[cur][nj][2], bf[cur][nj][3]);
                }
        }
    }

    // epilogue: direct register stores
    const int r0 = by * BM + wm * 32 + (lane >> 2);
    const int c0 = bx * BN + wn * 64 + (lane & 3) * 2;
    #pragma unroll
    for (int mi = 0; mi < 2; mi++)
        #pragma unroll
        for (int ni = 0; ni < 8; ni++) {
            float* p = out + (size_t)(r0 + mi * 16) * NROWS + c0 + ni * 8;
            *(float2*)(p)                     = make_float2(acc[mi][ni][0], acc[mi][ni][1]);
            *(float2*)(p + (size_t)8 * NROWS) = make_float2(acc[mi][ni][2], acc[mi][ni][3]);
        }
}

// ============================================================
// Kernel 3: per-row softmax stats + y_true write
// NOTE: y_out base is d_out + N*N + 1 -> only 4-byte aligned.
//       All y_out accesses MUST stay scalar.
// ============================================================
__global__ __launch_bounds__(256)
void row_reduce_kernel(const float* __restrict__ sim_dot,
                       const int*   __restrict__ labels,
                       float*       __restrict__ y_out) {
    __shared__ float s[NROWS];
    __shared__ int   slab[NROWS];
    __shared__ float red[8];

    const int i = blockIdx.x;
    const int t = threadIdx.x;
    const int li = labels[i];

    const float4* srow = (const float4*)(sim_dot + (size_t)i * NROWS);
    const int4*   lab4 = (const int4*)labels;

    float mx = -INFINITY;
    #pragma unroll
    for (int p = 0; p < 4; p++) {
        int j4 = p * 256 + t;
        float4 v = srow[j4];
        v.x /= TEMPF; v.y /= TEMPF; v.z /= TEMPF; v.w /= TEMPF;
        *(float4*)(s + j4 * 4) = v;
        *(int4*)(slab + j4 * 4) = lab4[j4];
        mx = fmaxf(mx, fmaxf(fmaxf(v.x, v.y), fmaxf(v.z, v.w)));
    }
    #pragma unroll
    for (int o = 16; o > 0; o >>= 1)
        mx = fmaxf(mx, __shfl_xor_sync(0xffffffffu, mx, o));
    if ((t & 31) == 0) red[t >> 5] = mx;
    __syncthreads();
    mx = red[0];
    #pragma unroll
    for (int w = 1; w < 8; w++) mx = fmaxf(mx, red[w]);
    __syncthreads();

    float sum_e = 0.f, sum_l = 0.f, cnt = 0.f;
    float* yrow = y_out + (size_t)i * NROWS;
    #pragma unroll
    for (int p = 0; p < 4; p++) {
        int j4 = p * 256 + t;
        float4 v = *(const float4*)(s + j4 * 4);
        int4 lb = *(const int4*)(slab + j4 * 4);
        float vv[4] = { v.x - mx, v.y - mx, v.z - mx, v.w - mx };
        int   ee[4] = { lb.x == li, lb.y == li, lb.z == li, lb.w == li };
        #pragma unroll
        for (int q = 0; q < 4; q++) {
            yrow[j4 * 4 + q] = ee[q] ? 1.0f : 0.0f;   // scalar store (4B-aligned base)
            sum_e += __expf(vv[q]);
            if (ee[q]) { sum_l += vv[q]; cnt += 1.f; }
        }
    }
    #pragma unroll
    for (int o = 16; o > 0; o >>= 1) {
        sum_e += __shfl_xor_sync(0xffffffffu, sum_e, o);
        sum_l += __shfl_xor_sync(0xffffffffu, sum_l, o);
        cnt   += __shfl_xor_sync(0xffffffffu, cnt,   o);
    }
    __shared__ float r_e[8], r_l[8], r_c[8];
    if ((t & 31) == 0) { r_e[t >> 5] = sum_e; r_l[t >> 5] = sum_l; r_c[t >> 5] = cnt; }
    __syncthreads();
    if (t == 0) {
        float te = 0.f, tl = 0.f, tc = 0.f;
        #pragma unroll
        for (int w = 0; w < 8; w++) { te += r_e[w]; tl += r_l[w]; tc += r_c[w]; }
        g_row_val[i] = tl / tc - __logf(te);
    }
}

// ============================================================
// Kernel 4: loss = -mean(row_val), 1024 threads
// ============================================================
__global__ __launch_bounds__(1024)
void loss_kernel(float* __restrict__ out_loss) {
    const int t = threadIdx.x;
    float4 v = *(const float4*)(g_row_val + t * 4);   // g_row_val is __align__(16)
    float sum = v.x + v.y + v.z + v.w;
    #pragma unroll
    for (int o = 16; o > 0; o >>= 1)
        sum += __shfl_xor_sync(0xffffffffu, sum, o);
    __shared__ float red[32];
    if ((t & 31) == 0) red[t >> 5] = sum;
    __syncthreads();
    if (t < 32) {
        float x = red[t];
        #pragma unroll
        for (int o = 16; o > 0; o >>= 1)
            x += __shfl_xor_sync(0xffffffffu, x, o);
        if (t == 0) out_loss[0] = -(x / (float)NROWS);
    }
}

// ============================================================
// launch
// ============================================================
extern "C" void kernel_launch(void* const* d_in, const int* in_sizes, int n_in,
                              void* d_out, int out_size) {
    const float* c      = (const float*)d_in[0];
    const float* ch     = (const float*)d_in[1];
    const int*   labels = (const int*)d_in[2];

    float* out   = (float*)d_out;
    float* sim   = out;
    float* loss  = out + (size_t)NROWS * NROWS;
    float* ytrue = out + (size_t)NROWS * NROWS + 1;

    normalize_split_kernel<<<2 * NROWS, 256>>>(c, ch);

    cudaFuncSetAttribute(gemm_kernel, cudaFuncAttributeMaxDynamicSharedMemorySize,
                         SMEM_DYN_BYTES);
    dim3 grid(NROWS / BN, NROWS / BM);
    gemm_kernel<<<grid, 256, SMEM_DYN_BYTES>>>(sim);

    row_reduce_kernel<<<NROWS, 256>>>(sim, labels, ytrue);

    loss_kernel<<<1, 1024>>>(loss);
}

// round 8
// speedup vs baseline: 1.9980x; 1.9980x over previous
#include <cuda_runtime.h>
#include <cuda_fp16.h>
#include <math.h>
#include <stdint.h>

#define NROWS 4096
#define DIM   1024
#define TEMPF 0.05f
#define EPSF  1e-8f

// single-pass fp16 GEMM: K = 1024 (normalized values are in [-1,1] -> fp16-safe)
#define KSTORE 1024
#define BM 128
#define BN 128
#define BK 64                       // fp16 per chunk = 128 bytes/row (SW128 atom)
#define NCHUNKS (KSTORE / BK)       // 16
#define NSTAGES 3
#define A_STAGE_BYTES (BM * 128)    // 16 KB
#define B_STAGE_BYTES (BN * 128)    // 16 KB
#define STAGE_BYTES   (A_STAGE_BYTES + B_STAGE_BYTES)   // 32 KB
#define SMEM_DYN_BYTES (NSTAGES * STAGE_BYTES)          // 96 KB -> 2 CTAs/SM

// -------- device scratch (no runtime allocation allowed) --------
__device__ __half g_a[(size_t)NROWS * KSTORE];   // cn  (fp16), 8 MB
__device__ __half g_b[(size_t)NROWS * KSTORE];   // chn (fp16), 8 MB
__device__ __align__(16) float g_row_val[NROWS];

// ============================================================
// helpers
// ============================================================
__device__ __forceinline__ uint32_t smem_u32(const void* p) {
    uint32_t a;
    asm("{ .reg .u64 t; cvta.to.shared.u64 t, %1; cvt.u32.u64 %0, t; }"
        : "=r"(a) : "l"(p));
    return a;
}

#define SW128(x) ((x) ^ (((x) >> 3) & 0x70))

__device__ __forceinline__ void cp_async16(uint32_t dst, const void* src) {
    asm volatile("cp.async.cg.shared.global [%0], [%1], 16;\n" :: "r"(dst), "l"(src));
}

__device__ __forceinline__ void ldsm_x4(uint32_t addr, uint32_t& r0, uint32_t& r1,
                                        uint32_t& r2, uint32_t& r3) {
    asm volatile("ldmatrix.sync.aligned.m8n8.x4.shared.b16 {%0,%1,%2,%3}, [%4];"
                 : "=r"(r0), "=r"(r1), "=r"(r2), "=r"(r3) : "r"(addr));
}

__device__ __forceinline__ void mma16816(float& c0, float& c1, float& c2, float& c3,
                                         uint32_t a0, uint32_t a1, uint32_t a2, uint32_t a3,
                                         uint32_t b0, uint32_t b1) {
    asm volatile(
        "mma.sync.aligned.m16n8k16.row.col.f32.f16.f16.f32 "
        "{%0,%1,%2,%3}, {%4,%5,%6,%7}, {%8,%9}, {%0,%1,%2,%3};"
        : "+f"(c0), "+f"(c1), "+f"(c2), "+f"(c3)
        : "r"(a0), "r"(a1), "r"(a2), "r"(a3), "r"(b0), "r"(b1));
}

// ============================================================
// Kernel 1: row-normalize -> fp16 into g_a / g_b
// ============================================================
__global__ __launch_bounds__(256)
void normalize_kernel(const float* __restrict__ c, const float* __restrict__ ch) {
    int row = blockIdx.x;
    bool isC = (row < NROWS);
    int r = isC ? row : row - NROWS;
    const float4* srow = (const float4*)((isC ? c : ch) + (size_t)r * DIM);

    int t = threadIdx.x;
    float4 v = srow[t];
    float ssq = v.x * v.x + v.y * v.y + v.z * v.z + v.w * v.w;

    #pragma unroll
    for (int o = 16; o > 0; o >>= 1)
        ssq += __shfl_xor_sync(0xffffffffu, ssq, o);

    __shared__ float wsum[8];
    if ((t & 31) == 0) wsum[t >> 5] = ssq;
    __syncthreads();
    float tot = 0.f;
    #pragma unroll
    for (int w = 0; w < 8; w++) tot += wsum[w];

    float rinv = 1.0f / fmaxf(sqrtf(tot), EPSF);

    union { __half h[4]; uint2 u; } ph;
    ph.h[0] = __float2half_rn(v.x * rinv);
    ph.h[1] = __float2half_rn(v.y * rinv);
    ph.h[2] = __float2half_rn(v.z * rinv);
    ph.h[3] = __float2half_rn(v.w * rinv);

    __half* dst = (isC ? g_a : g_b) + (size_t)r * KSTORE + t * 4;
    *(uint2*)dst = ph.u;
}

// ============================================================
// Kernel 2: mma.sync fp16 GEMM, 128x128 tile, K=1024
// 8 warps as 4(M) x 2(N); warp tile 32x64; mma m16n8k16  (R6 loop shape)
// ============================================================
__device__ __forceinline__ void load_chunk(const __half* gA, const __half* gB,
                                           int kc, uint32_t sA, uint32_t sB, int t) {
    int ke = kc * BK;
    #pragma unroll
    for (int i = 0; i < 4; i++) {                 // A: 128 rows * 8 blocks / 256 thr
        int idx = i * 256 + t;
        int r = idx >> 3, cb = idx & 7;
        cp_async16(sA + SW128(r * 128 + cb * 16), gA + (size_t)r * KSTORE + ke + cb * 8);
    }
    #pragma unroll
    for (int i = 0; i < 4; i++) {                 // B: same shape
        int idx = i * 256 + t;
        int r = idx >> 3, cb = idx & 7;
        cp_async16(sB + SW128(r * 128 + cb * 16), gB + (size_t)r * KSTORE + ke + cb * 8);
    }
    asm volatile("cp.async.commit_group;\n" ::: "memory");
}

__global__ __launch_bounds__(256)
void gemm_kernel(float* __restrict__ out) {
    extern __shared__ char dyn_smem[];

    const int t    = threadIdx.x;
    const int wid  = t >> 5;
    const int lane = t & 31;
    const int wm   = wid >> 1;          // 0..3  (M warp)
    const int wn   = wid & 1;           // 0..1  (N warp)
    const int bx   = blockIdx.x;        // N tile
    const int by   = blockIdx.y;        // M tile

    uint32_t smem = smem_u32(dyn_smem);

    const __half* gA = g_a + (size_t)by * BM * KSTORE;
    const __half* gB = g_b + (size_t)bx * BN * KSTORE;

    float acc[2][8][4];
    #pragma unroll
    for (int mi = 0; mi < 2; mi++)
        #pragma unroll
        for (int ni = 0; ni < 8; ni++)
            #pragma unroll
            for (int q = 0; q < 4; q++) acc[mi][ni][q] = 0.f;

    // prologue: 2 chunks in flight
    load_chunk(gA, gB, 0, smem, smem + A_STAGE_BYTES, t);
    load_chunk(gA, gB, 1, smem + STAGE_BYTES, smem + STAGE_BYTES + A_STAGE_BYTES, t);

    const int a_row_in16 = lane & 15;
    const int a_kadd     = ((lane >> 4) & 1) * 16;
    const int b_row_in16 = (lane & 7) + (((lane >> 4) & 1) << 3);
    const int b_kadd     = ((lane >> 3) & 1) * 16;

    for (int kc = 0; kc < NCHUNKS; kc++) {
        if (kc + 2 < NCHUNKS) {
            int s = (kc + 2) % NSTAGES;
            load_chunk(gA, gB, kc + 2, smem + s * STAGE_BYTES,
                       smem + s * STAGE_BYTES + A_STAGE_BYTES, t);
        } else {
            asm volatile("cp.async.commit_group;\n" ::: "memory");
        }

        asm volatile("cp.async.wait_group 2;\n" ::: "memory");
        __syncthreads();

        uint32_t sA = smem + (kc % NSTAGES) * STAGE_BYTES;
        uint32_t sB = sA + A_STAGE_BYTES;

        #pragma unroll
        for (int ks = 0; ks < 4; ks++) {          // 4 x k16 per 64-elem chunk
            const int kb = ks * 32;

            uint32_t af[2][4];
            #pragma unroll
            for (int mi = 0; mi < 2; mi++) {
                int row = wm * 32 + mi * 16 + a_row_in16;
                ldsm_x4(sA + SW128(row * 128 + kb + a_kadd),
                        af[mi][0], af[mi][1], af[mi][2], af[mi][3]);
            }

            uint32_t bf[4][4];
            #pragma unroll
            for (int nj = 0; nj < 4; nj++) {
                int row = wn * 64 + nj * 16 + b_row_in16;
                ldsm_x4(sB + SW128(row * 128 + kb + b_kadd),
                        bf[nj][0], bf[nj][1], bf[nj][2], bf[nj][3]);
            }

            #pragma unroll
            for (int mi = 0; mi < 2; mi++)
                #pragma unroll
                for (int nj = 0; nj < 4; nj++) {
                    mma16816(acc[mi][nj * 2 + 0][0], acc[mi][nj * 2 + 0][1],
                             acc[mi][nj * 2 + 0][2], acc[mi][nj * 2 + 0][3],
                             af[mi][0], af[mi][1], af[mi][2], af[mi][3],
                             bf[nj][0], bf[nj][1]);
                    mma16816(acc[mi][nj * 2 + 1][0], acc[mi][nj * 2 + 1][1],
                             acc[mi][nj * 2 + 1][2], acc[mi][nj * 2 + 1][3],
                             af[mi][0], af[mi][1], af[mi][2], af[mi][3],
                             bf[nj][2], bf[nj][3]);
                }
        }
        __syncthreads();
    }

    // epilogue: direct register stores
    const int r0 = by * BM + wm * 32 + (lane >> 2);
    const int c0 = bx * BN + wn * 64 + (lane & 3) * 2;
    #pragma unroll
    for (int mi = 0; mi < 2; mi++)
        #pragma unroll
        for (int ni = 0; ni < 8; ni++) {
            float* p = out + (size_t)(r0 + mi * 16) * NROWS + c0 + ni * 8;
            *(float2*)(p)                     = make_float2(acc[mi][ni][0], acc[mi][ni][1]);
            *(float2*)(p + (size_t)8 * NROWS) = make_float2(acc[mi][ni][2], acc[mi][ni][3]);
        }
}

// ============================================================
// Kernel 3: per-row softmax stats + y_true write
// NOTE: y_out base is d_out + N*N + 1 -> only 4-byte aligned.
//       All y_out accesses MUST stay scalar.
// ============================================================
__global__ __launch_bounds__(256)
void row_reduce_kernel(const float* __restrict__ sim_dot,
                       const int*   __restrict__ labels,
                       float*       __restrict__ y_out) {
    __shared__ float s[NROWS];
    __shared__ int   slab[NROWS];
    __shared__ float red[8];

    const int i = blockIdx.x;
    const int t = threadIdx.x;
    const int li = labels[i];

    const float4* srow = (const float4*)(sim_dot + (size_t)i * NROWS);
    const int4*   lab4 = (const int4*)labels;

    float mx = -INFINITY;
    #pragma unroll
    for (int p = 0; p < 4; p++) {
        int j4 = p * 256 + t;
        float4 v = srow[j4];
        v.x /= TEMPF; v.y /= TEMPF; v.z /= TEMPF; v.w /= TEMPF;
        *(float4*)(s + j4 * 4) = v;
        *(int4*)(slab + j4 * 4) = lab4[j4];
        mx = fmaxf(mx, fmaxf(fmaxf(v.x, v.y), fmaxf(v.z, v.w)));
    }
    #pragma unroll
    for (int o = 16; o > 0; o >>= 1)
        mx = fmaxf(mx, __shfl_xor_sync(0xffffffffu, mx, o));
    if ((t & 31) == 0) red[t >> 5] = mx;
    __syncthreads();
    mx = red[0];
    #pragma unroll
    for (int w = 1; w < 8; w++) mx = fmaxf(mx, red[w]);
    __syncthreads();

    float sum_e = 0.f, sum_l = 0.f, cnt = 0.f;
    float* yrow = y_out + (size_t)i * NROWS;
    #pragma unroll
    for (int p = 0; p < 4; p++) {
        int j4 = p * 256 + t;
        float4 v = *(const float4*)(s + j4 * 4);
        int4 lb = *(const int4*)(slab + j4 * 4);
        float vv[4] = { v.x - mx, v.y - mx, v.z - mx, v.w - mx };
        int   ee[4] = { lb.x == li, lb.y == li, lb.z == li, lb.w == li };
        #pragma unroll
        for (int q = 0; q < 4; q++) {
            yrow[j4 * 4 + q] = ee[q] ? 1.0f : 0.0f;   // scalar store (4B-aligned base)
            sum_e += __expf(vv[q]);
            if (ee[q]) { sum_l += vv[q]; cnt += 1.f; }
        }
    }
    #pragma unroll
    for (int o = 16; o > 0; o >>= 1) {
        sum_e += __shfl_xor_sync(0xffffffffu, sum_e, o);
        sum_l += __shfl_xor_sync(0xffffffffu, sum_l, o);
        cnt   += __shfl_xor_sync(0xffffffffu, cnt,   o);
    }
    __shared__ float r_e[8], r_l[8], r_c[8];
    if ((t & 31) == 0) { r_e[t >> 5] = sum_e; r_l[t >> 5] = sum_l; r_c[t >> 5] = cnt; }
    __syncthreads();
    if (t == 0) {
        float te = 0.f, tl = 0.f, tc = 0.f;
        #pragma unroll
        for (int w = 0; w < 8; w++) { te += r_e[w]; tl += r_l[w]; tc += r_c[w]; }
        g_row_val[i] = tl / tc - __logf(te);
    }
}

// ============================================================
// Kernel 4: loss = -mean(row_val), 1024 threads
// ============================================================
__global__ __launch_bounds__(1024)
void loss_kernel(float* __restrict__ out_loss) {
    const int t = threadIdx.x;
    float4 v = *(const float4*)(g_row_val + t * 4);   // g_row_val is __align__(16)
    float sum = v.x + v.y + v.z + v.w;
    #pragma unroll
    for (int o = 16; o > 0; o >>= 1)
        sum += __shfl_xor_sync(0xffffffffu, sum, o);
    __shared__ float red[32];
    if ((t & 31) == 0) red[t >> 5] = sum;
    __syncthreads();
    if (t < 32) {
        float x = red[t];
        #pragma unroll
        for (int o = 16; o > 0; o >>= 1)
            x += __shfl_xor_sync(0xffffffffu, x, o);
        if (t == 0) out_loss[0] = -(x / (float)NROWS);
    }
}

// ============================================================
// launch
// ============================================================
extern "C" void kernel_launch(void* const* d_in, const int* in_sizes, int n_in,
                              void* d_out, int out_size) {
    const float* c      = (const float*)d_in[0];
    const float* ch     = (const float*)d_in[1];
    const int*   labels = (const int*)d_in[2];

    float* out   = (float*)d_out;
    float* sim   = out;
    float* loss  = out + (size_t)NROWS * NROWS;
    float* ytrue = out + (size_t)NROWS * NROWS + 1;

    normalize_kernel<<<2 * NROWS, 256>>>(c, ch);

    cudaFuncSetAttribute(gemm_kernel, cudaFuncAttributeMaxDynamicSharedMemorySize,
                         SMEM_DYN_BYTES);
    dim3 grid(NROWS / BN, NROWS / BM);
    gemm_kernel<<<grid, 256, SMEM_DYN_BYTES>>>(sim);

    row_reduce_kernel<<<NROWS, 256>>>(sim, labels, ytrue);

    loss_kernel<<<1, 1024>>>(loss);
}